// round 17
// baseline (speedup 1.0000x reference)
#include <cuda_runtime.h>
#include <cuda_fp16.h>
#include <math.h>
#include <stdint.h>

#define NH     16
#define NKV    4
#define HDIM   128
#define BATCH  2
#define SEQ    2048
#define DMODEL 2048
#define NTOK   (BATCH*SEQ)
#define NQKV   (DMODEL + 2*NKV*HDIM)   // 3072

// ---------------------------------------------------------------------------
// scratch
// ---------------------------------------------------------------------------
static __device__ __half g_qraw[NTOK * NH * HDIM];   // pre-rope q (fp16)
static __device__ __half g_kraw[NTOK * NKV * HDIM];  // pre-rope k (fp16)

static __device__ __half g_qh[NTOK * NH * HDIM];
static __device__ __half g_kbh[NTOK * NKV * HDIM];
static __device__ __half g_vbh[NTOK * NKV * HDIM];

static __device__ __half g_xh[NTOK * DMODEL];
static __device__ __half g_cth[NTOK * DMODEL];
static __device__ __half g_wqkv[NQKV * DMODEL];
static __device__ __half g_woh[DMODEL * DMODEL];

// ---------------------------------------------------------------------------
// helpers
// ---------------------------------------------------------------------------
__device__ __forceinline__ uint32_t smem_u32(const void* p) {
  uint32_t a;
  asm("{ .reg .u64 t; cvta.to.shared.u64 t, %1; cvt.u32.u64 %0, t; }" : "=r"(a) : "l"(p));
  return a;
}

#define LDSM4(R, addr)                                                        \
  asm volatile("ldmatrix.sync.aligned.m8n8.x4.shared.b16 {%0,%1,%2,%3}, [%4];"\
    : "=r"((R)[0]), "=r"((R)[1]), "=r"((R)[2]), "=r"((R)[3]) : "r"(addr))

#define LDSM4T(R, addr)                                                       \
  asm volatile("ldmatrix.sync.aligned.m8n8.x4.trans.shared.b16 {%0,%1,%2,%3}, [%4];"\
    : "=r"((R)[0]), "=r"((R)[1]), "=r"((R)[2]), "=r"((R)[3]) : "r"(addr))

#define MMAF16(D, A, b0v, b1v)                                                \
  asm volatile("mma.sync.aligned.m16n8k16.row.col.f32.f16.f16.f32 "           \
    "{%0,%1,%2,%3}, {%4,%5,%6,%7}, {%8,%9}, {%0,%1,%2,%3};"                   \
    : "+f"((D)[0]), "+f"((D)[1]), "+f"((D)[2]), "+f"((D)[3])                  \
    : "r"((A)[0]), "r"((A)[1]), "r"((A)[2]), "r"((A)[3]), "r"(b0v), "r"(b1v))

#define CP_ASYNC16(dst, src) \
  asm volatile("cp.async.cg.shared.global [%0], [%1], 16;" :: "r"(dst), "l"(src))
#define CP_COMMIT() asm volatile("cp.async.commit_group;")

// ---------------------------------------------------------------------------
// fp32 -> fp16 convert
// ---------------------------------------------------------------------------
__global__ void __launch_bounds__(256) cvt_kernel(const float* __restrict__ src,
    __half* __restrict__ dst, int n4) {
  int i = blockIdx.x * 256 + threadIdx.x;
  if (i < n4) {
    float4 v = *(const float4*)(src + (size_t)i * 4);
    __half2 a, b;
    a.x = __float2half_rn(v.x); a.y = __float2half_rn(v.y);
    b.x = __float2half_rn(v.z); b.y = __float2half_rn(v.w);
    *(__half2*)(dst + (size_t)i * 4) = a;
    *(__half2*)(dst + (size_t)i * 4 + 2) = b;
  }
}

// W [K,N] fp32 -> transposed fp16 [N,K]
__global__ void __launch_bounds__(256) wcvt_kernel(const float* __restrict__ W,
    __half* __restrict__ th, int K, int N) {
  __shared__ float t[32][33];
  int n0 = blockIdx.x * 32, k0 = blockIdx.y * 32;
  int x = threadIdx.x, y = threadIdx.y;
  #pragma unroll
  for (int i = 0; i < 4; i++)
    t[y * 4 + i][x] = W[(size_t)(k0 + y * 4 + i) * N + n0 + x];
  __syncthreads();
  #pragma unroll
  for (int i = 0; i < 4; i++) {
    int n = n0 + y * 4 + i;
    th[(size_t)n * K + k0 + x] = __float2half_rn(t[x][y * 4 + i]);
  }
}

// ---------------------------------------------------------------------------
// GEMM core (fp16 operands, fp32 accum), 128x128 tile, BK=32, 2-stage.
// ---------------------------------------------------------------------------
#define GBM 128
#define GBN 128
#define GBK 32
#define RSTRIDE 80
#define TILE_BYTES (128 * RSTRIDE)
#define STG_BYTES (2 * TILE_BYTES)
#define GEMM_SMEM (2 * STG_BYTES)

struct GemmAcc { float a[2][8][4]; };

__device__ __forceinline__ void gemm_core(
    const __half* __restrict__ Ah, const __half* __restrict__ Bh,
    int bm, int bn, int K, uint32_t sbase, GemmAcc& acc) {
  int tid = threadIdx.x;
  int wid = tid >> 5, lane = tid & 31;
  int wm = wid >> 1, wn = wid & 1;
  int nc = K / GBK;

  auto load_chunk = [&](int c, int buf) {
    int k0 = c * GBK;
    #pragma unroll
    for (int i = 0; i < 4; i++) {
      int idx = tid + i * 256;
      int t = i >> 1;
      int r = (idx >> 2) & 127;
      int g = idx & 3;
      uint32_t dst = sbase + buf * STG_BYTES + t * TILE_BYTES + r * RSTRIDE + g * 16;
      const __half* src = (t ? Bh : Ah) + (size_t)((t ? bn : bm) + r) * K + k0 + g * 8;
      CP_ASYNC16(dst, src);
    }
    CP_COMMIT();
  };

  #pragma unroll
  for (int mi = 0; mi < 2; mi++)
    #pragma unroll
    for (int ni = 0; ni < 8; ni++)
      #pragma unroll
      for (int j = 0; j < 4; j++) acc.a[mi][ni][j] = 0.f;

  load_chunk(0, 0);
  int lrow = lane & 15, lk8 = (lane >> 4) * 8;

  for (int c = 0; c < nc; c++) {
    if (c + 1 < nc) {
      load_chunk(c + 1, (c + 1) & 1);
      asm volatile("cp.async.wait_group 1;");
    } else {
      asm volatile("cp.async.wait_group 0;");
    }
    __syncthreads();

    uint32_t b0 = sbase + (c & 1) * STG_BYTES;
    uint32_t aHs = b0, bHs = b0 + TILE_BYTES;

    #pragma unroll
    for (int kk = 0; kk < GBK; kk += 16) {
      uint32_t ah[2][4];
      uint32_t aoff = (uint32_t)(wm * 32 + lrow) * RSTRIDE + (kk + lk8) * 2;
      LDSM4(ah[0], aHs + aoff);
      LDSM4(ah[1], aHs + aoff + 16 * RSTRIDE);
      #pragma unroll
      for (int p = 0; p < 4; p++) {
        uint32_t boff = (uint32_t)(wn * 64 + p * 16 + lrow) * RSTRIDE + (kk + lk8) * 2;
        uint32_t h[4];
        LDSM4(h, bHs + boff);
        #pragma unroll
        for (int mi = 0; mi < 2; mi++) {
          MMAF16(acc.a[mi][2 * p],     ah[mi], h[0], h[2]);
          MMAF16(acc.a[mi][2 * p + 1], ah[mi], h[1], h[3]);
        }
      }
    }
    __syncthreads();
  }
}

// merged QKV projection; all outputs fp16.
// cols [0,2048) -> g_qraw; [2048,2560) -> g_kraw; [2560,3072) -> g_vbh.
__global__ void __launch_bounds__(256, 2) gemm_qkv_kernel(
    const __half* __restrict__ Ah, const __half* __restrict__ Bh) {
  extern __shared__ char smem[];
  uint32_t sbase = smem_u32(smem);
  int bm = blockIdx.y * GBM, bn = blockIdx.x * GBN;
  GemmAcc acc;
  gemm_core(Ah, Bh, bm, bn, DMODEL, sbase, acc);

  int wid = threadIdx.x >> 5, lane = threadIdx.x & 31;
  int wm = wid >> 1, wn = wid & 1;
  int gid = lane >> 2, cid = lane & 3;
  #pragma unroll
  for (int mi = 0; mi < 2; mi++)
    #pragma unroll
    for (int ni = 0; ni < 8; ni++) {
      int row = bm + wm * 32 + mi * 16 + gid;
      int col = bn + wn * 64 + ni * 8 + cid * 2;
      #pragma unroll
      for (int half = 0; half < 2; half++) {
        __half2 hh;
        hh.x = __float2half_rn(acc.a[mi][ni][2 * half]);
        hh.y = __float2half_rn(acc.a[mi][ni][2 * half + 1]);
        int rr = row + half * 8;
        if (col < DMODEL)
          *(__half2*)(g_qraw + (size_t)rr * DMODEL + col) = hh;
        else if (col < DMODEL + 512)
          *(__half2*)(g_kraw + (size_t)rr * 512 + (col - DMODEL)) = hh;
        else
          *(__half2*)(g_vbh + (size_t)rr * 512 + (col - DMODEL - 512)) = hh;
      }
    }
}

__global__ void __launch_bounds__(256, 2) gemm_out_kernel(
    const __half* __restrict__ Ah, const __half* __restrict__ Bh,
    float* __restrict__ Cf) {
  extern __shared__ char smem[];
  uint32_t sbase = smem_u32(smem);
  int bm = blockIdx.y * GBM, bn = blockIdx.x * GBN;
  GemmAcc acc;
  gemm_core(Ah, Bh, bm, bn, DMODEL, sbase, acc);

  int wid = threadIdx.x >> 5, lane = threadIdx.x & 31;
  int wm = wid >> 1, wn = wid & 1;
  int gid = lane >> 2, cid = lane & 3;
  #pragma unroll
  for (int mi = 0; mi < 2; mi++)
    #pragma unroll
    for (int ni = 0; ni < 8; ni++) {
      int row = bm + wm * 32 + mi * 16 + gid;
      int col = bn + wn * 64 + ni * 8 + cid * 2;
      *(float2*)(Cf + (size_t)row * DMODEL + col) =
          make_float2(acc.a[mi][ni][0], acc.a[mi][ni][1]);
      *(float2*)(Cf + (size_t)(row + 8) * DMODEL + col) =
          make_float2(acc.a[mi][ni][2], acc.a[mi][ni][3]);
    }
}

// ---------------------------------------------------------------------------
// RoPE + L2 norm (fp16 in, fp16 out)
// ---------------------------------------------------------------------------
__global__ void __launch_bounds__(64) rope_norm_kernel() {
  int tok = blockIdx.x;
  int r = blockIdx.y;
  size_t off = (r < NH) ? ((size_t)tok * NH + r) * HDIM
                        : ((size_t)tok * NKV + (r - NH)) * HDIM;
  const __half* base = (r < NH) ? g_qraw + off : g_kraw + off;
  __half* dst = (r < NH) ? g_qh + off : g_kbh + off;
  int pos = tok & (SEQ - 1);
  int i = threadIdx.x;
  __half2 tv = *(const __half2*)(base + 2 * i);
  float t0 = __half2float(tv.x), t1 = __half2float(tv.y);
  float inv = exp2f((float)(2 * i) * (-13.287712379549449f / 128.0f));
  float ang = (float)pos * inv;
  float sn, cs;
  sincosf(ang, &sn, &cs);
  float r0 = t0 * cs - t1 * sn;
  float r1 = t0 * sn + t1 * cs;
  float ss = r0 * r0 + r1 * r1;
  #pragma unroll
  for (int o = 16; o; o >>= 1) ss += __shfl_xor_sync(0xffffffffu, ss, o);
  __shared__ float part[2];
  if ((i & 31) == 0) part[i >> 5] = ss;
  __syncthreads();
  float sc = rsqrtf((part[0] + part[1]) * (1.0f / 128.0f) + 1e-6f);
  __half2 hh;
  hh.x = __float2half_rn(r0 * sc);
  hh.y = __float2half_rn(r1 * sc);
  *(__half2*)(dst + 2 * i) = hh;
}

// ---------------------------------------------------------------------------
// MMA attention: fp16, double-buffered staging, parity accumulators,
// AV P-fragments built in registers (no P smem staging).
// ---------------------------------------------------------------------------
#define SCW 2056
#define PAD_STR 272
#define OFF_QH 131584
#define OFF_K0 (OFF_QH + 16*PAD_STR)
#define OFF_K1 (OFF_K0 + 128*PAD_STR)
#define OFF_RED (OFF_K1 + 128*PAD_STR)
#define ATTN_SMEM (OFF_RED + 128)

__global__ void __launch_bounds__(256, 1) attn_mma_kernel(
    float* __restrict__ attn_out, int write_attn) {
  extern __shared__ char smc[];
  float* s_scores = (float*)smc;
  float* s_red = (float*)(smc + OFF_RED);
  uint32_t sb = smem_u32(smc);

  int qb = gridDim.x - 1 - blockIdx.x;
  int h = blockIdx.y, b = blockIdx.z;
  int hk = h >> 2;
  int tid = threadIdx.x, w = tid >> 5, lane = tid & 31;
  int kend = qb * 16 + 16;
  int nch = (kend + 127) >> 7;
  const float SC = 0.08838834764831845f;
  int lrow = lane & 15, lhi = lane >> 4;
  uint32_t kbuf[2] = {sb + OFF_K0, sb + OFF_K1};

  auto load_kv = [&](const __half* srcbase, int kc, uint32_t dstbase) {
    #pragma unroll
    for (int i = 0; i < 8; i++) {
      int idx = tid + i * 256;
      int r = idx >> 4, g = idx & 15;
      const __half* src = srcbase + ((size_t)(b * SEQ + kc + r) * NKV + hk) * HDIM + g * 8;
      CP_ASYNC16(dstbase + r * PAD_STR + g * 16, src);
    }
    CP_COMMIT();
  };

  {
    int r = tid >> 4, g = tid & 15;
    size_t go = ((size_t)(b * SEQ + qb * 16 + r) * NH + h) * HDIM + g * 8;
    *(uint4*)(smc + OFF_QH + r * PAD_STR + g * 16) = *(const uint4*)(g_qh + go);
  }
  load_kv(g_kbh, 0, kbuf[0]);
  __syncthreads();

  uint32_t aH[8][4];
  #pragma unroll
  for (int kk = 0; kk < 8; kk++) {
    uint32_t off = lrow * PAD_STR + kk * 32 + lhi * 16;
    LDSM4(aH[kk], sb + OFF_QH + off);
  }

  // ---- scores ----
  for (int ci = 0; ci < nch; ci++) {
    int kc = ci << 7;
    if (ci + 1 < nch) {
      load_kv(g_kbh, kc + 128, kbuf[(ci + 1) & 1]);
      asm volatile("cp.async.wait_group 1;");
    } else {
      asm volatile("cp.async.wait_group 0;");
    }
    __syncthreads();

    int n0 = w * 16;
    if (kc + n0 < kend) {
      uint32_t kb = kbuf[ci & 1];
      float acc[2][2][4];
      #pragma unroll
      for (int pp = 0; pp < 2; pp++)
        #pragma unroll
        for (int nt = 0; nt < 2; nt++)
          #pragma unroll
          for (int j = 0; j < 4; j++) acc[pp][nt][j] = 0.f;
      #pragma unroll
      for (int kk = 0; kk < 8; kk++) {
        uint32_t off = (uint32_t)(n0 + lrow) * PAD_STR + kk * 32 + lhi * 16;
        uint32_t bh[4];
        LDSM4(bh, kb + off);
        MMAF16(acc[kk & 1][0], aH[kk], bh[0], bh[2]);
        MMAF16(acc[kk & 1][1], aH[kk], bh[1], bh[3]);
      }
      int r0 = lane >> 2, c0 = (lane & 3) * 2;
      int qs0 = qb * 16;
      #pragma unroll
      for (int nt = 0; nt < 2; nt++) {
        int col = kc + n0 + nt * 8 + c0;
        float e0 = acc[0][nt][0] + acc[1][nt][0];
        float e1 = acc[0][nt][1] + acc[1][nt][1];
        float e2 = acc[0][nt][2] + acc[1][nt][2];
        float e3 = acc[0][nt][3] + acc[1][nt][3];
        s_scores[r0 * SCW + col]           = (col     <= qs0 + r0)     ? e0 * SC : -1e30f;
        s_scores[r0 * SCW + col + 1]       = (col + 1 <= qs0 + r0)     ? e1 * SC : -1e30f;
        s_scores[(r0 + 8) * SCW + col]     = (col     <= qs0 + r0 + 8) ? e2 * SC : -1e30f;
        s_scores[(r0 + 8) * SCW + col + 1] = (col + 1 <= qs0 + r0 + 8) ? e3 * SC : -1e30f;
      }
    }
    __syncthreads();
  }

  // ---- softmax stats ----
  {
    int qi = tid >> 4, r = tid & 15;
    float m = -1e30f;
    for (int j = r; j < kend; j += 16) m = fmaxf(m, s_scores[qi * SCW + j]);
    #pragma unroll
    for (int o = 8; o; o >>= 1) m = fmaxf(m, __shfl_xor_sync(0xffffffffu, m, o));
    float s = 0.f;
    for (int j = r; j < kend; j += 16) s += __expf(s_scores[qi * SCW + j] - m);
    #pragma unroll
    for (int o = 8; o; o >>= 1) s += __shfl_xor_sync(0xffffffffu, s, o);
    if (r == 0) { s_red[qi] = m; s_red[16 + qi] = 1.0f / s; }
  }
  __syncthreads();

  // ---- probs: normalize once into s_scores; optional gmem write ----
  {
    float* ab = attn_out + ((size_t)(b * NH + h) * SEQ + (size_t)qb * 16) * SEQ;
    for (int idx = tid; idx < 16 * 512; idx += 256) {
      int qi = idx >> 9, j4 = (idx & 511) * 4;
      float m = s_red[qi], inv = s_red[16 + qi];
      float4 p = {0, 0, 0, 0};
      if (j4 < kend) {
        p.x = __expf(s_scores[qi * SCW + j4] - m) * inv;
        if (j4 + 1 < kend) p.y = __expf(s_scores[qi * SCW + j4 + 1] - m) * inv;
        if (j4 + 2 < kend) p.z = __expf(s_scores[qi * SCW + j4 + 2] - m) * inv;
        if (j4 + 3 < kend) p.w = __expf(s_scores[qi * SCW + j4 + 3] - m) * inv;
        s_scores[qi * SCW + j4]     = p.x;
        s_scores[qi * SCW + j4 + 1] = p.y;
        s_scores[qi * SCW + j4 + 2] = p.z;
        s_scores[qi * SCW + j4 + 3] = p.w;
      }
      if (write_attn) *(float4*)(ab + (size_t)qi * SEQ + j4) = p;
    }
  }
  __syncthreads();

  // ---- AV: P fragments from registers, V double-buffered ----
  float oacc[2][2][4];
  #pragma unroll
  for (int pp = 0; pp < 2; pp++)
    #pragma unroll
    for (int nt = 0; nt < 2; nt++)
      #pragma unroll
      for (int j = 0; j < 4; j++) oacc[pp][nt][j] = 0.f;

  int gid = lane >> 2, cid2 = (lane & 3) * 2;
  load_kv(g_vbh, 0, kbuf[0]);
  for (int ci = 0; ci < nch; ci++) {
    int kc = ci << 7;
    if (ci + 1 < nch) {
      load_kv(g_vbh, kc + 128, kbuf[(ci + 1) & 1]);
      asm volatile("cp.async.wait_group 1;");
    } else {
      asm volatile("cp.async.wait_group 0;");
    }
    __syncthreads();

    uint32_t vb = kbuf[ci & 1];
    int kkmax = min(8, (kend - kc) >> 4);
    for (int kk = 0; kk < kkmax; kk++) {
      // P A-fragment: rows gid/gid+8, k-cols kc+kk*16 + {cid2,cid2+1, +8}
      int base = kc + kk * 16 + cid2;
      const float* pr0 = s_scores + (size_t)gid * SCW;
      const float* pr1 = s_scores + (size_t)(gid + 8) * SCW;
      uint32_t pa[4];
      __half2 h0; h0.x = __float2half_rn(pr0[base]);     h0.y = __float2half_rn(pr0[base + 1]);
      __half2 h1; h1.x = __float2half_rn(pr1[base]);     h1.y = __float2half_rn(pr1[base + 1]);
      __half2 h2; h2.x = __float2half_rn(pr0[base + 8]); h2.y = __float2half_rn(pr0[base + 9]);
      __half2 h3; h3.x = __float2half_rn(pr1[base + 8]); h3.y = __float2half_rn(pr1[base + 9]);
      pa[0] = *(uint32_t*)&h0; pa[1] = *(uint32_t*)&h1;
      pa[2] = *(uint32_t*)&h2; pa[3] = *(uint32_t*)&h3;

      uint32_t vOff = (uint32_t)(kk * 16 + lrow) * PAD_STR + w * 32 + lhi * 16;
      uint32_t vh[4];
      LDSM4T(vh, vb + vOff);
      MMAF16(oacc[kk & 1][0], pa, vh[0], vh[1]);
      MMAF16(oacc[kk & 1][1], pa, vh[2], vh[3]);
    }
    __syncthreads();
  }

  // epilogue: ctx fp16 [tok, H*HD]
  {
    #pragma unroll
    for (int nt = 0; nt < 2; nt++) {
      int col = w * 16 + nt * 8 + cid2;
      #pragma unroll
      for (int half = 0; half < 2; half++) {
        __half2 hh;
        hh.x = __float2half_rn(oacc[0][nt][2 * half] + oacc[1][nt][2 * half]);
        hh.y = __float2half_rn(oacc[0][nt][2 * half + 1] + oacc[1][nt][2 * half + 1]);
        size_t o = ((size_t)(b * SEQ + qb * 16 + gid + half * 8)) * DMODEL
                 + h * HDIM + col;
        *(__half2*)(g_cth + o) = hh;
      }
    }
  }
}

// ---------------------------------------------------------------------------
extern "C" void kernel_launch(void* const* d_in, const int* in_sizes, int n_in,
                              void* d_out, int out_size) {
  const float* x  = (const float*)d_in[0];
  const float* Wq = (const float*)d_in[1];
  const float* Wk = (const float*)d_in[2];
  const float* Wv = (const float*)d_in[3];
  const float* Wo = (const float*)d_in[4];
  float* out = (float*)d_out;
  float* attn = out + (size_t)NTOK * DMODEL;
  long long need = (long long)NTOK * DMODEL + (long long)BATCH * NH * SEQ * SEQ;
  int write_attn = ((long long)out_size >= need) ? 1 : 0;

  __half *xh, *cth, *wqkv, *woh;
  cudaGetSymbolAddress((void**)&xh, g_xh);
  cudaGetSymbolAddress((void**)&cth, g_cth);
  cudaGetSymbolAddress((void**)&wqkv, g_wqkv);
  cudaGetSymbolAddress((void**)&woh, g_woh);

  cudaFuncSetAttribute(gemm_qkv_kernel, cudaFuncAttributeMaxDynamicSharedMemorySize,
                       GEMM_SMEM);
  cudaFuncSetAttribute(gemm_out_kernel, cudaFuncAttributeMaxDynamicSharedMemorySize,
                       GEMM_SMEM);
  cudaFuncSetAttribute(attn_mma_kernel, cudaFuncAttributeMaxDynamicSharedMemorySize,
                       ATTN_SMEM);

  cvt_kernel<<<(NTOK * DMODEL / 4 + 255) / 256, 256>>>(x, xh, NTOK * DMODEL / 4);
  wcvt_kernel<<<dim3((NH*HDIM)/32, DMODEL/32), dim3(32, 8)>>>(Wq, wqkv, DMODEL, NH*HDIM);
  wcvt_kernel<<<dim3((NKV*HDIM)/32, DMODEL/32), dim3(32, 8)>>>(
      Wk, wqkv + (size_t)DMODEL * DMODEL, DMODEL, NKV*HDIM);
  wcvt_kernel<<<dim3((NKV*HDIM)/32, DMODEL/32), dim3(32, 8)>>>(
      Wv, wqkv + (size_t)(DMODEL + 512) * DMODEL, DMODEL, NKV*HDIM);
  wcvt_kernel<<<dim3(DMODEL/32, DMODEL/32), dim3(32, 8)>>>(Wo, woh, DMODEL, DMODEL);

  gemm_qkv_kernel<<<dim3(NQKV/GBN, NTOK/GBM), 256, GEMM_SMEM>>>(xh, wqkv);

  rope_norm_kernel<<<dim3(NTOK, NH + NKV), 64>>>();

  attn_mma_kernel<<<dim3(SEQ / 16, NH, BATCH), 256, ATTN_SMEM>>>(attn, write_attn);

  gemm_out_kernel<<<dim3(DMODEL/GBN, NTOK/GBM), 256, GEMM_SMEM>>>(cth, woh, out);
}